// round 1
// baseline (speedup 1.0000x reference)
#include <cuda_runtime.h>
#include <cuda_bf16.h>

// Conv2D 15x15 valid cross-correlation, 4096x4096 fp32 -> 4082x4082 fp32.
// Column-register-blocked direct convolution.
//
// Layout:
//   block = 256 threads, each thread computes one output column x, TY=16 rows.
//   block tile: 256 (x) x 16 (y). grid = (16, 256).
//   smem tile: 30 rows x 270 cols (halo 14 each dim), weights 15x15 in smem.
//
// Hot loop (per kx, kx loop NOT unrolled to bound I$ footprint):
//   load 30-float column segment (conflict-free LDS, lane-consecutive),
//   load 15-weight column to regs, then 15x16 fully unrolled FFMAs.

#define H_IN   4096
#define W_IN   4096
#define KH     15
#define KW     15
#define OH     (H_IN - KH + 1)   // 4082
#define OW     (W_IN - KW + 1)   // 4082

#define BX     256               // block x width == threads
#define TY     16                // outputs per thread in y
#define TROWS  (TY + KH - 1)     // 30 smem rows
#define TCOLS  (BX + KW - 1)     // 270 valid smem cols
#define TPITCH 272               // padded pitch (floats)

__global__ __launch_bounds__(256)
void conv15_kernel(const float* __restrict__ X,
                   const float* __restrict__ Wt,
                   const float* __restrict__ bias,
                   float* __restrict__ out)
{
    __shared__ float tile[TROWS * TPITCH];
    __shared__ float wsh[KH * KW];

    const int tid = threadIdx.x;
    const int gx0 = blockIdx.x * BX;
    const int gy0 = blockIdx.y * TY;

    if (tid < KH * KW) wsh[tid] = Wt[tid];

    // Cooperative fill of the 30x270 input tile, coalesced along x.
    // Clamp out-of-range indices: those values only feed accumulators that
    // are never stored (outputs beyond 4081), so any in-bounds value is fine.
    #pragma unroll
    for (int i = tid; i < TROWS * TCOLS; i += BX) {
        int r = i / TCOLS;
        int c = i - r * TCOLS;
        int gy = gy0 + r; if (gy > H_IN - 1) gy = H_IN - 1;
        int gx = gx0 + c; if (gx > W_IN - 1) gx = W_IN - 1;
        tile[r * TPITCH + c] = X[gy * W_IN + gx];
    }
    __syncthreads();

    float acc[TY];
    #pragma unroll
    for (int t = 0; t < TY; t++) acc[t] = 0.0f;

    // kx loop deliberately rolled: body ~290 SASS instructions, fits L0 I$.
    #pragma unroll 1
    for (int kx = 0; kx < KW; kx++) {
        // Column segment: tile[i][tid + kx], lane-consecutive -> conflict-free.
        float seg[TROWS];
        #pragma unroll
        for (int i = 0; i < TROWS; i++)
            seg[i] = tile[i * TPITCH + tid + kx];

        float wc[KH];
        #pragma unroll
        for (int ky = 0; ky < KH; ky++)
            wc[ky] = wsh[ky * KW + kx];

        #pragma unroll
        for (int ky = 0; ky < KH; ky++) {
            #pragma unroll
            for (int ty = 0; ty < TY; ty++)
                acc[ty] = fmaf(seg[ty + ky], wc[ky], acc[ty]);
        }
    }

    const float b = bias[0];
    const int ox = gx0 + tid;
    if (ox < OW) {
        #pragma unroll
        for (int ty = 0; ty < TY; ty++) {
            int oy = gy0 + ty;
            if (oy < OH)
                out[oy * OW + ox] = acc[ty] + b;
        }
    }
}

extern "C" void kernel_launch(void* const* d_in, const int* in_sizes, int n_in,
                              void* d_out, int out_size)
{
    const float* X    = (const float*)d_in[0];  // [4096,4096]
    const float* Wt   = (const float*)d_in[1];  // [15,15]
    const float* bias = (const float*)d_in[2];  // [1]
    float* out        = (float*)d_out;          // [4082,4082]

    dim3 grid((OW + BX - 1) / BX,   // 16
              (OH + TY - 1) / TY);  // 256
    conv15_kernel<<<grid, BX>>>(X, Wt, bias, out);
}